// round 2
// baseline (speedup 1.0000x reference)
#include <cuda_runtime.h>
#include <cuda_bf16.h>

#define BB 32
#define TT 8
#define NN 512
#define FF 4
#define COC 12

// Scratch (allocation-free rule: __device__ globals)
__device__ float g_wscr[68];                 // [0:4) v_src, [4:8) v_dst, [8:56) Mih[f*12+g], [56:68) cx
__device__ float g_gates[BB * TT * NN * 12]; // gates_x per (b,t,n)
__device__ float g_gru[BB * TT * NN * FF];   // conv input [B][8ch][512][4]

__device__ __forceinline__ float ex2f(float a) {
    float r;
    asm("ex2.approx.f32 %0, %1;" : "=f"(r) : "f"(a));
    return r;
}
#define L2E 1.4426950408889634f

__device__ __forceinline__ float sigm(float x) {
    float e = ex2f(-x * L2E);
    return __fdividef(1.f, 1.f + e);
}
__device__ __forceinline__ float tanh_(float x) {
    float e = ex2f(x * (2.f * L2E));
    return __fdividef(e - 1.f, e + 1.f);
}

// ---------------- K0: fold weights ----------------
// v_src = gat_W @ att_src, v_dst = gat_W @ att_dst (4-vectors)
// Mih[f][g] = sum_h gat_W[f,h] * W_ih[g,h]   (4x12)
// cx[g] = b_ih[g] + sum_h gat_bias[h] * W_ih[g,h]
__global__ void k_prep(const float* __restrict__ gatW, const float* __restrict__ attS,
                       const float* __restrict__ attD, const float* __restrict__ gatB,
                       const float* __restrict__ Wih, const float* __restrict__ bih) {
    int t = threadIdx.x;
    if (t < 4) {
        float s = 0.f, d = 0.f;
        for (int h = 0; h < 64; h++) {
            float w = gatW[t * 64 + h];
            s += w * attS[h];
            d += w * attD[h];
        }
        g_wscr[t] = s;
        g_wscr[4 + t] = d;
    }
    if (t < 48) {
        int f = t / 12, g = t % 12;
        float s = 0.f;
        for (int h = 0; h < 64; h++) s += gatW[f * 64 + h] * Wih[g * 64 + h];
        g_wscr[8 + t] = s;
    }
    if (t < 12) {
        float s = bih[t];
        for (int h = 0; h < 64; h++) s += gatB[h] * Wih[t * 64 + h];
        g_wscr[56 + t] = s;
    }
}

// ---------------- K1: fused GAT softmax + (alpha@x) + gates ----------------
// grid (4, B*T), block 128. Block q handles rows i in [q*128,(q+1)*128) of (b,t).
__global__ __launch_bounds__(128) void k_gat(const float* __restrict__ x,
                                             const float* __restrict__ adj) {
    __shared__ float4 xs[NN];
    __shared__ float asrc[NN];
    __shared__ float red[4];

    int bt = blockIdx.y;
    int q = blockIdx.x;
    int tid = threadIdx.x;

    const float4* xb = (const float4*)(x + (size_t)bt * NN * FF);
#pragma unroll
    for (int j = tid; j < NN; j += 128) xs[j] = xb[j];

    float vs0 = g_wscr[0], vs1 = g_wscr[1], vs2 = g_wscr[2], vs3 = g_wscr[3];
    float vd0 = g_wscr[4], vd1 = g_wscr[5], vd2 = g_wscr[6], vd3 = g_wscr[7];
    __syncthreads();

    float mx = -1e30f;
#pragma unroll
    for (int j = tid; j < NN; j += 128) {
        float4 v = xs[j];
        float a = v.x * vs0 + v.y * vs1 + v.z * vs2 + v.w * vs3;
        asrc[j] = a;
        mx = fmaxf(mx, a);
    }
#pragma unroll
    for (int o = 16; o; o >>= 1) mx = fmaxf(mx, __shfl_xor_sync(0xffffffffu, mx, o));
    if ((tid & 31) == 0) red[tid >> 5] = mx;
    __syncthreads();
    float mas = fmaxf(fmaxf(red[0], red[1]), fmaxf(red[2], red[3]));

    int i = q * 128 + tid;
    float4 xi = xs[i];
    float ad = xi.x * vd0 + xi.y * vd1 + xi.z * vd2 + xi.w * vd3;
    // m_i = max_j leaky(ad + a_src[j]) = leaky(ad + max_j a_src[j])  (monotone)
    float t0 = ad + mas;
    float mi = fmaxf(t0, 0.2f * t0);
    float nm = -mi * L2E;

    const float* ap = adj + (size_t)bt * NN * NN + i;
    float s = 0.f, a0 = 0.f, a1 = 0.f, a2 = 0.f, a3 = 0.f;

    for (int j = 0; j < NN; j += 8) {
        float av[8];
#pragma unroll
        for (int u = 0; u < 8; u++) av[u] = ap[(j + u) * NN];
#pragma unroll
        for (int u = 0; u < 8; u++) {
            float t2 = ad + asrc[j + u];
            float e = fmaxf(t2, 0.2f * t2);
            float p = ex2f(__fmaf_rn(e, L2E, nm));
            bool valid = (av[u] != 0.f) || ((j + u) == i);
            if (!valid) p = 0.f;
            float4 xj = xs[j + u];
            s += p;
            a0 = __fmaf_rn(p, xj.x, a0);
            a1 = __fmaf_rn(p, xj.y, a1);
            a2 = __fmaf_rn(p, xj.z, a2);
            a3 = __fmaf_rn(p, xj.w, a3);
        }
    }

    float inv = __fdividef(1.f, s);
    float ax0 = a0 * inv, ax1 = a1 * inv, ax2 = a2 * inv, ax3 = a3 * inv;

    float* gp = g_gates + ((size_t)bt * NN + i) * 12;
#pragma unroll
    for (int g = 0; g < 12; g++) {
        gp[g] = g_wscr[56 + g] + ax0 * g_wscr[8 + g] + ax1 * g_wscr[20 + g] +
                ax2 * g_wscr[32 + g] + ax3 * g_wscr[44 + g];
    }
}

// ---------------- K2: GRU (hidden=4) over the "view" sequence ----------------
// Sequence p = b*512 + t*64 + n_hi; time step tt = n&7; input row n = n_hi*8+tt.
// Writes conv input g_gru[b][tt][t*64+n_hi][f] = h after step tt.
__global__ __launch_bounds__(256) void k_gru(const float* __restrict__ Whh,
                                             const float* __restrict__ bhh) {
    __shared__ float w[48], bb[12];
    if (threadIdx.x < 48) w[threadIdx.x] = Whh[threadIdx.x];
    if (threadIdx.x < 12) bb[threadIdx.x] = bhh[threadIdx.x];
    __syncthreads();

    int p = blockIdx.x * 256 + threadIdx.x;
    int b = p >> 9, rem = p & 511, t = rem >> 6, nhi = rem & 63;

    float h[4] = {0.f, 0.f, 0.f, 0.f};
    const float* gb = g_gates + ((size_t)((b * TT + t) * NN) + nhi * 8) * 12;

    for (int tt = 0; tt < 8; tt++) {
        const float* gx = gb + tt * 12;
        float nh[4];
#pragma unroll
        for (int k = 0; k < 4; k++) {
            float ghr = bb[k]     + w[k * 4 + 0] * h[0] + w[k * 4 + 1] * h[1] + w[k * 4 + 2] * h[2] + w[k * 4 + 3] * h[3];
            float ghz = bb[4 + k] + w[(4 + k) * 4 + 0] * h[0] + w[(4 + k) * 4 + 1] * h[1] + w[(4 + k) * 4 + 2] * h[2] + w[(4 + k) * 4 + 3] * h[3];
            float ghn = bb[8 + k] + w[(8 + k) * 4 + 0] * h[0] + w[(8 + k) * 4 + 1] * h[1] + w[(8 + k) * 4 + 2] * h[2] + w[(8 + k) * 4 + 3] * h[3];
            float r = sigm(gx[k] + ghr);
            float z = sigm(gx[4 + k] + ghz);
            float nc = tanh_(gx[8 + k] + r * ghn);
            nh[k] = (1.f - z) * nc + z * h[k];
        }
#pragma unroll
        for (int k = 0; k < 4; k++) h[k] = nh[k];
        ((float4*)g_gru)[(b * TT + tt) * NN + t * 64 + nhi] =
            make_float4(h[0], h[1], h[2], h[3]);
    }
}

// ---------------- K3: Conv2d(8->12, 3x3, pad1 over [512,4]) + Linear(4->2) ----------------
__global__ __launch_bounds__(256) void k_conv(const float* __restrict__ convW,
                                              const float* __restrict__ convB,
                                              const float* __restrict__ outW,
                                              const float* __restrict__ outB,
                                              float* __restrict__ out) {
    int idx = blockIdx.x * 256 + threadIdx.x; // ((b*12+co)*512+hp)
    int hp = idx & 511;
    int co = (idx >> 9) % 12;
    int b = idx / (12 * 512);

    float cb = convB[co];
    float y0 = cb, y1 = cb, y2 = cb, y3 = cb;

#pragma unroll
    for (int ci = 0; ci < 8; ci++) {
        const float4* base = (const float4*)g_gru + (b * TT + ci) * NN;
#pragma unroll
        for (int kh = 0; kh < 3; kh++) {
            int r = hp + kh - 1;
            if (r < 0 || r > 511) continue;
            float4 rv = base[r];
            const float* wk = convW + ((co * 8 + ci) * 3 + kh) * 3;
            float w0 = wk[0], w1 = wk[1], w2 = wk[2];
            y0 += rv.x * w1 + rv.y * w2;
            y1 += rv.x * w0 + rv.y * w1 + rv.z * w2;
            y2 += rv.y * w0 + rv.z * w1 + rv.w * w2;
            y3 += rv.z * w0 + rv.w * w1;
        }
    }

    float o0 = outB[0] + y0 * outW[0] + y1 * outW[1] + y2 * outW[2] + y3 * outW[3];
    float o1 = outB[1] + y0 * outW[4] + y1 * outW[5] + y2 * outW[6] + y3 * outW[7];
    out[2 * idx] = o0;
    out[2 * idx + 1] = o1;
}

extern "C" void kernel_launch(void* const* d_in, const int* in_sizes, int n_in,
                              void* d_out, int out_size) {
    const float* x    = (const float*)d_in[0];
    const float* adj  = (const float*)d_in[1];
    const float* gatW = (const float*)d_in[2];
    const float* attS = (const float*)d_in[3];
    const float* attD = (const float*)d_in[4];
    const float* gatB = (const float*)d_in[5];
    const float* Wih  = (const float*)d_in[6];
    const float* Whh  = (const float*)d_in[7];
    const float* bih  = (const float*)d_in[8];
    const float* bhh  = (const float*)d_in[9];
    const float* cW   = (const float*)d_in[10];
    const float* cB   = (const float*)d_in[11];
    const float* oW   = (const float*)d_in[12];
    const float* oB   = (const float*)d_in[13];
    float* out = (float*)d_out;

    k_prep<<<1, 64>>>(gatW, attS, attD, gatB, Wih, bih);
    dim3 g1(4, BB * TT);
    k_gat<<<g1, 128>>>(x, adj);
    k_gru<<<(BB * NN) / 256, 256>>>(Whh, bhh);          // 16384 threads
    k_conv<<<(BB * COC * NN) / 256, 256>>>(cW, cB, oW, oB, out);
}

// round 3
// speedup vs baseline: 1.1988x; 1.1988x over previous
#include <cuda_runtime.h>
#include <cuda_bf16.h>

#define BB 32
#define TT 8
#define NN 512
#define FF 4
#define COC 12
#define JS 4
#define L2E 1.4426950408889634f

// Scratch (__device__ globals; no allocation allowed)
__device__ float  g_wscr[68];                   // [0:4) v_src, [4:8) v_dst, [8:56) M[f*12+g], [56:68) cx
__device__ float4 g_pA[BB * TT * JS * NN];      // partial sum_j p*x_j
__device__ float  g_pS[BB * TT * JS * NN];      // partial sum_j p
__device__ float  g_gru[BB * TT * NN * FF];     // conv input [B][8ch][512][4]

__device__ __forceinline__ float ex2f(float a) {
    float r;
    asm("ex2.approx.f32 %0, %1;" : "=f"(r) : "f"(a));
    return r;
}
__device__ __forceinline__ float sigm(float x) {
    float e = ex2f(-x * L2E);
    return __fdividef(1.f, 1.f + e);
}
__device__ __forceinline__ float tanh_(float x) {
    float e = ex2f(x * (2.f * L2E));
    return __fdividef(e - 1.f, e + 1.f);
}

// ---------------- K0: fold weights ----------------
__global__ void k_prep(const float* __restrict__ gatW, const float* __restrict__ attS,
                       const float* __restrict__ attD, const float* __restrict__ gatB,
                       const float* __restrict__ Wih, const float* __restrict__ bih) {
    int t = threadIdx.x;
    if (t < 4) {
        float s = 0.f, d = 0.f;
        for (int h = 0; h < 64; h++) {
            float w = gatW[t * 64 + h];
            s += w * attS[h];
            d += w * attD[h];
        }
        g_wscr[t] = s;
        g_wscr[4 + t] = d;
    }
    if (t < 48) {
        int f = t / 12, g = t % 12;
        float s = 0.f;
        for (int h = 0; h < 64; h++) s += gatW[f * 64 + h] * Wih[g * 64 + h];
        g_wscr[8 + t] = s;
    }
    if (t < 12) {
        float s = bih[t];
        for (int h = 0; h < 64; h++) s += gatB[h] * Wih[t * 64 + h];
        g_wscr[56 + t] = s;
    }
}

// ---------------- K1: fused GAT softmax partials ----------------
// grid (JS, B*T), block 128. Thread handles 4 rows i = 4*tid..4*tid+3,
// j-slice [js*128, js*128+128). adj loaded as float4 (coalesced 512B/warp).
__global__ __launch_bounds__(128) void k_gat(const float* __restrict__ x,
                                             const float* __restrict__ adj) {
    __shared__ float4 xs[NN];
    __shared__ float as2[NN];   // asrc * L2E
    __shared__ float red[4];

    int bt = blockIdx.y;
    int js = blockIdx.x;
    int tid = threadIdx.x;

    const float4* xb = (const float4*)(x + (size_t)bt * NN * FF);
#pragma unroll
    for (int j = tid; j < NN; j += 128) xs[j] = xb[j];

    float vs0 = g_wscr[0], vs1 = g_wscr[1], vs2 = g_wscr[2], vs3 = g_wscr[3];
    float vd0 = g_wscr[4], vd1 = g_wscr[5], vd2 = g_wscr[6], vd3 = g_wscr[7];
    __syncthreads();

    float mx = -1e30f;
#pragma unroll
    for (int j = tid; j < NN; j += 128) {
        float4 v = xs[j];
        float a = v.x * vs0 + v.y * vs1 + v.z * vs2 + v.w * vs3;
        as2[j] = a * L2E;
        mx = fmaxf(mx, a);
    }
#pragma unroll
    for (int o = 16; o; o >>= 1) mx = fmaxf(mx, __shfl_xor_sync(0xffffffffu, mx, o));
    if ((tid & 31) == 0) red[tid >> 5] = mx;
    __syncthreads();
    float mas = fmaxf(fmaxf(red[0], red[1]), fmaxf(red[2], red[3])); // max_j a_src (unscaled)

    int i0 = tid * 4;
    float ad2[4], c8[4];
#pragma unroll
    for (int r = 0; r < 4; r++) {
        float4 xi = xs[i0 + r];
        float a = xi.x * vd0 + xi.y * vd1 + xi.z * vd2 + xi.w * vd3;
        float t0 = a + mas;
        float mi = fmaxf(t0, 0.2f * t0);      // exact row max of leaky(ad+asrc_j)
        float nm = -mi * L2E;
        ad2[r] = __fmaf_rn(a, L2E, nm);       // a*L2E + nm
        c8[r] = 0.8f * nm;
        // arg = max(v, v*0.2 + 0.8*nm) where v = ad2 + asrc*L2E  (== leaky(u)*L2E + nm)
    }

    const float4* ap = (const float4*)(adj + (size_t)bt * NN * NN) + tid;
    int jbase = js * (NN / JS);

    float sr[4] = {0.f, 0.f, 0.f, 0.f};
    float4 ac[4];
#pragma unroll
    for (int r = 0; r < 4; r++) ac[r] = make_float4(0.f, 0.f, 0.f, 0.f);

    for (int jo = 0; jo < NN / JS; jo += 4) {
        float4 av[4];
#pragma unroll
        for (int u = 0; u < 4; u++) av[u] = ap[(size_t)(jbase + jo + u) * (NN / 4)];
#pragma unroll
        for (int u = 0; u < 4; u++) {
            int j = jbase + jo + u;
            float aj = as2[j];
            float4 xj = xs[j];
            float am[4] = {av[u].x, av[u].y, av[u].z, av[u].w};
#pragma unroll
            for (int r = 0; r < 4; r++) {
                float v = ad2[r] + aj;
                float arg = fmaxf(v, __fmaf_rn(v, 0.2f, c8[r]));
                float p = ex2f(arg);
                bool valid = (am[r] != 0.f) || (j == i0 + r);
                if (!valid) p = 0.f;
                sr[r] += p;
                ac[r].x = __fmaf_rn(p, xj.x, ac[r].x);
                ac[r].y = __fmaf_rn(p, xj.y, ac[r].y);
                ac[r].z = __fmaf_rn(p, xj.z, ac[r].z);
                ac[r].w = __fmaf_rn(p, xj.w, ac[r].w);
            }
        }
    }

    int base = (bt * JS + js) * NN + i0;
#pragma unroll
    for (int r = 0; r < 4; r++) {
        g_pA[base + r] = ac[r];
        g_pS[base + r] = sr[r];
    }
}

// ---------------- K2: combine partials + gates + GRU (hidden=4) ----------------
// View-bug sequence: p = b*512 + t*64 + nhi; step tt uses row n = nhi*8+tt.
__global__ __launch_bounds__(256) void k_gru(const float* __restrict__ Whh,
                                             const float* __restrict__ bhh) {
    __shared__ float w[48], bb[12], wm[68];
    if (threadIdx.x < 48) w[threadIdx.x] = Whh[threadIdx.x];
    if (threadIdx.x < 12) bb[threadIdx.x] = bhh[threadIdx.x];
    if (threadIdx.x < 68) wm[threadIdx.x] = g_wscr[threadIdx.x];
    __syncthreads();

    int p = blockIdx.x * 256 + threadIdx.x;
    int b = p >> 9, rem = p & 511, t = rem >> 6, nhi = rem & 63;
    int bt = b * TT + t;

    float h[4] = {0.f, 0.f, 0.f, 0.f};

    for (int tt = 0; tt < 8; tt++) {
        int n = nhi * 8 + tt;
        float Ax = 0.f, Ay = 0.f, Az = 0.f, Aw = 0.f, S = 0.f;
#pragma unroll
        for (int js = 0; js < JS; js++) {
            int idx = (bt * JS + js) * NN + n;
            float4 a = g_pA[idx];
            Ax += a.x; Ay += a.y; Az += a.z; Aw += a.w;
            S += g_pS[idx];
        }
        float inv = __fdividef(1.f, S);
        float ax0 = Ax * inv, ax1 = Ay * inv, ax2 = Az * inv, ax3 = Aw * inv;

        float gx[12];
#pragma unroll
        for (int g = 0; g < 12; g++)
            gx[g] = wm[56 + g] + ax0 * wm[8 + g] + ax1 * wm[20 + g] +
                    ax2 * wm[32 + g] + ax3 * wm[44 + g];

        float nh[4];
#pragma unroll
        for (int k = 0; k < 4; k++) {
            float ghr = bb[k]     + w[k * 4 + 0] * h[0] + w[k * 4 + 1] * h[1] + w[k * 4 + 2] * h[2] + w[k * 4 + 3] * h[3];
            float ghz = bb[4 + k] + w[(4 + k) * 4 + 0] * h[0] + w[(4 + k) * 4 + 1] * h[1] + w[(4 + k) * 4 + 2] * h[2] + w[(4 + k) * 4 + 3] * h[3];
            float ghn = bb[8 + k] + w[(8 + k) * 4 + 0] * h[0] + w[(8 + k) * 4 + 1] * h[1] + w[(8 + k) * 4 + 2] * h[2] + w[(8 + k) * 4 + 3] * h[3];
            float r = sigm(gx[k] + ghr);
            float z = sigm(gx[4 + k] + ghz);
            float nc = tanh_(gx[8 + k] + r * ghn);
            nh[k] = (1.f - z) * nc + z * h[k];
        }
#pragma unroll
        for (int k = 0; k < 4; k++) h[k] = nh[k];
        ((float4*)g_gru)[(b * TT + tt) * NN + t * 64 + nhi] =
            make_float4(h[0], h[1], h[2], h[3]);
    }
}

// ---------------- K3: Conv2d(8->12, 3x3, pad1 over [512,4]) + Linear(4->2) ----------------
// grid (3 co-groups, B), block 512 (= hp). Stages each input plane in smem once.
__global__ __launch_bounds__(512) void k_conv(const float* __restrict__ convW,
                                              const float* __restrict__ convB,
                                              const float* __restrict__ outW,
                                              const float* __restrict__ outB,
                                              float* __restrict__ out) {
    __shared__ float4 tile[NN];
    __shared__ float wsm[4 * 8 * 9];
    __shared__ float ow[8], ob[2], cb[4];

    int cog = blockIdx.x;   // co group: 4 channels
    int b = blockIdx.y;
    int tid = threadIdx.x;  // = hp
    int hp = tid;

    if (tid < 288) wsm[tid] = convW[cog * 4 * 72 + tid];
    if (tid < 8) ow[tid] = outW[tid];
    if (tid < 2) ob[tid] = outB[tid];
    if (tid < 4) cb[tid] = convB[cog * 4 + tid];
    __syncthreads();

    float y[4][4];
#pragma unroll
    for (int q = 0; q < 4; q++) {
        float c = cb[q];
        y[q][0] = c; y[q][1] = c; y[q][2] = c; y[q][3] = c;
    }

    for (int ci = 0; ci < 8; ci++) {
        __syncthreads();
        tile[tid] = ((const float4*)g_gru)[(b * TT + ci) * NN + tid];
        __syncthreads();
        float4 zz = make_float4(0.f, 0.f, 0.f, 0.f);
        float4 rm = (hp > 0) ? tile[hp - 1] : zz;
        float4 r0 = tile[hp];
        float4 rp = (hp < NN - 1) ? tile[hp + 1] : zz;
#pragma unroll
        for (int q = 0; q < 4; q++) {
            const float* wk = &wsm[(q * 8 + ci) * 9];
            float4 rv;
#pragma unroll
            for (int kh = 0; kh < 3; kh++) {
                rv = (kh == 0) ? rm : ((kh == 1) ? r0 : rp);
                float w0 = wk[kh * 3 + 0], w1 = wk[kh * 3 + 1], w2 = wk[kh * 3 + 2];
                y[q][0] += rv.x * w1 + rv.y * w2;
                y[q][1] += rv.x * w0 + rv.y * w1 + rv.z * w2;
                y[q][2] += rv.y * w0 + rv.z * w1 + rv.w * w2;
                y[q][3] += rv.z * w0 + rv.w * w1;
            }
        }
    }

#pragma unroll
    for (int q = 0; q < 4; q++) {
        int co = cog * 4 + q;
        int idx = (b * COC + co) * NN + hp;
        float o0 = ob[0] + y[q][0] * ow[0] + y[q][1] * ow[1] + y[q][2] * ow[2] + y[q][3] * ow[3];
        float o1 = ob[1] + y[q][0] * ow[4] + y[q][1] * ow[5] + y[q][2] * ow[6] + y[q][3] * ow[7];
        out[2 * idx] = o0;
        out[2 * idx + 1] = o1;
    }
}

extern "C" void kernel_launch(void* const* d_in, const int* in_sizes, int n_in,
                              void* d_out, int out_size) {
    const float* x    = (const float*)d_in[0];
    const float* adj  = (const float*)d_in[1];
    const float* gatW = (const float*)d_in[2];
    const float* attS = (const float*)d_in[3];
    const float* attD = (const float*)d_in[4];
    const float* gatB = (const float*)d_in[5];
    const float* Wih  = (const float*)d_in[6];
    const float* Whh  = (const float*)d_in[7];
    const float* bih  = (const float*)d_in[8];
    const float* bhh  = (const float*)d_in[9];
    const float* cW   = (const float*)d_in[10];
    const float* cB   = (const float*)d_in[11];
    const float* oW   = (const float*)d_in[12];
    const float* oB   = (const float*)d_in[13];
    float* out = (float*)d_out;

    k_prep<<<1, 64>>>(gatW, attS, attD, gatB, Wih, bih);
    dim3 g1(JS, BB * TT);
    k_gat<<<g1, 128>>>(x, adj);
    k_gru<<<(BB * NN) / 256, 256>>>(Whh, bhh);
    dim3 g3(3, BB);
    k_conv<<<g3, 512>>>(cW, cB, oW, oB, out);
}